// round 13
// baseline (speedup 1.0000x reference)
#include <cuda_runtime.h>
#include <cuda_fp16.h>
#include <math.h>
#include <stdint.h>

#define HID   1024
#define SEQ   512
#define RIMG  196
#define BATCH 32
#define NCT   8
#define MT    128
#define NT    128
#define KC    64
#define NCHUNK (HID / KC)
#define ROWB  144
#define VERB  (128 * ROWB)
#define STAGEB (2 * VERB)
#define WV_OFF  (2 * STAGEB)
#define RED_OFF (WV_OFF + 512)
#define SMEM_DYN (RED_OFF + 1024 + 256)

#define IMG_MT (BATCH * RIMG / MT)    // 49
#define DNS_MT (BATCH * SEQ / MT)     // 128

#define VSPLIT 7
#define USPLIT 16

// ---------------- scratch ----------------
__device__ float g_part1[NCT * BATCH * RIMG];
__device__ float g_part2[NCT * BATCH * SEQ];
__device__ float g_vp[VSPLIT * BATCH * HID];
__device__ float g_up[USPLIT * BATCH * HID];

__device__ __half g_wi_h[HID * HID];
__device__ __half g_wd_h[HID * HID];

// ---------------- helpers ----------------
__device__ __forceinline__ uint32_t smem_u32(const void* p) {
    uint32_t a;
    asm("{ .reg .u64 t; cvta.to.shared.u64 t, %1; cvt.u32.u64 %0, t; }" : "=r"(a) : "l"(p));
    return a;
}
__device__ __forceinline__ void ldsm4(uint32_t* r, uint32_t addr) {
    asm volatile("ldmatrix.sync.aligned.m8n8.x4.shared.b16 {%0,%1,%2,%3}, [%4];"
                 : "=r"(r[0]), "=r"(r[1]), "=r"(r[2]), "=r"(r[3]) : "r"(addr));
}
__device__ __forceinline__ void mma16816(float* c, const uint32_t* a,
                                         uint32_t b0, uint32_t b1) {
    asm volatile(
        "mma.sync.aligned.m16n8k16.row.col.f32.f16.f16.f32 "
        "{%0,%1,%2,%3}, {%4,%5,%6,%7}, {%8,%9}, {%0,%1,%2,%3};"
        : "+f"(c[0]), "+f"(c[1]), "+f"(c[2]), "+f"(c[3])
        : "r"(a[0]), "r"(a[1]), "r"(a[2]), "r"(a[3]), "r"(b0), "r"(b1));
}
#define CP16(s, g) \
    asm volatile("cp.async.cg.shared.global [%0], [%1], 16;" :: "r"(s), "l"(g) : "memory")
#define CP_COMMIT() asm volatile("cp.async.commit_group;" ::: "memory")

__device__ __forceinline__ float fast_tanh(float x) {
    return 1.f - 2.f / (__expf(2.f * x) + 1.f);
}
__device__ __forceinline__ float warpRedMax(float v) {
#pragma unroll
    for (int o = 16; o > 0; o >>= 1) v = fmaxf(v, __shfl_xor_sync(0xffffffffu, v, o));
    return v;
}
__device__ __forceinline__ float warpRedSum(float v) {
#pragma unroll
    for (int o = 16; o > 0; o >>= 1) v += __shfl_xor_sync(0xffffffffu, v, o);
    return v;
}

// pack 8 fp32 (2 float4) -> uint4 of 8 fp16
__device__ __forceinline__ uint4 pack8(float4 a, float4 c) {
    __half2 h0 = __floats2half2_rn(a.x, a.y);
    __half2 h1 = __floats2half2_rn(a.z, a.w);
    __half2 h2 = __floats2half2_rn(c.x, c.y);
    __half2 h3 = __floats2half2_rn(c.z, c.w);
    uint4 w;
    w.x = *reinterpret_cast<uint32_t*>(&h0);
    w.y = *reinterpret_cast<uint32_t*>(&h1);
    w.z = *reinterpret_cast<uint32_t*>(&h2);
    w.w = *reinterpret_cast<uint32_t*>(&h3);
    return w;
}

// ---------------------------------------------------------------------------
// fp32 -> fp16 for the two weight matrices only
// ---------------------------------------------------------------------------
#define NB_W (HID * HID / 4096)    // 256
__global__ __launch_bounds__(256)
void tohalf2(const float* __restrict__ i0, __half* __restrict__ o0,
             const float* __restrict__ i1, __half* __restrict__ o1)
{
    const int b = blockIdx.x;
    const float* in; __half* out; int base;
    if (b < NB_W) { in = i0; out = o0; base = b; }
    else          { in = i1; out = o1; base = b - NB_W; }
    const int i = base * 256 + threadIdx.x;
    const float4* p = (const float4*)in + (size_t)i * 4;
    float4 f[4];
#pragma unroll
    for (int j = 0; j < 4; j++) f[j] = __ldg(p + j);
    uint4* o = (uint4*)out + (size_t)i * 2;
    o[0] = pack8(f[0], f[1]);
    o[1] = pack8(f[2], f[3]);
}

// ---------------------------------------------------------------------------
// fused GEMM for BOTH score paths; activations converted fp32->fp16 inline.
// A: fp32 LDG prefetch (2 groups of 4 float4) -> cvt -> STS.
// B: fp16 weights via cp.async (pre-converted).
// ---------------------------------------------------------------------------
__global__ __launch_bounds__(256, 2)
void gemm_h2(const float* __restrict__ Xd, const __half* __restrict__ Wd,
             const float* __restrict__ wvd, float* __restrict__ partd,
             const float* __restrict__ Xi, const __half* __restrict__ Wi,
             const float* __restrict__ wvi, float* __restrict__ parti)
{
    extern __shared__ char smem[];
    const uint32_t sb = smem_u32(smem);
    const int tid = threadIdx.x, lane = tid & 31, wid = tid >> 5;
    const int ntile = blockIdx.x;

    const float* X;
    const __half* W;
    const float* wvec;
    float* part;
    int mtile, Ntot;
    if (blockIdx.y < DNS_MT) {
        X = Xd; W = Wd; wvec = wvd; part = partd;
        mtile = blockIdx.y; Ntot = BATCH * SEQ;
    } else {
        X = Xi; W = Wi; wvec = wvi; part = parti;
        mtile = blockIdx.y - DNS_MT; Ntot = BATCH * RIMG;
    }

    float* wvsh = (float*)(smem + WV_OFF);
    float* red  = (float*)(smem + RED_OFF);
    if (tid < 128) wvsh[tid] = wvec[ntile * NT + tid];

    const int row  = tid >> 1;
    const int half = tid & 1;
    // fp32 A: float4 base of this thread's 32-float half-row per chunk
    const float4* pAf = (const float4*)(X + (size_t)(mtile * MT + row) * HID) + half * 8;
    const char*   pB  = (const char*)(W + (size_t)(ntile * NT + row) * HID) + half * 64;
    const uint32_t stA = (uint32_t)(row * ROWB + half * 64);           // fp16 dest base

    const int m_off = (wid & 3) * 32;
    const int n_off = (wid >> 2) * 64;
    const int lm_row  = lane & 15;
    const int lm_colb = (lane & 16) ? 16 : 0;

    float acc[2][8][4];
#pragma unroll
    for (int t = 0; t < 2; t++)
#pragma unroll
        for (int n = 0; n < 8; n++)
#pragma unroll
            for (int j = 0; j < 4; j++) acc[t][n][j] = 0.f;

#define ISSUE_B(ci)                                                \
    do {                                                           \
        const uint32_t s0 = sb + ((ci) & 1) * STAGEB + VERB + stA; \
        const char* gB = pB + (size_t)(ci) * 128;                  \
        CP16(s0,      gB);                                         \
        CP16(s0 + 16, gB + 16);                                    \
        CP16(s0 + 32, gB + 32);                                    \
        CP16(s0 + 48, gB + 48);                                    \
        CP_COMMIT();                                               \
    } while (0)

// load 4 float4 of A for chunk ci, group g (g in {0,1})
#define LOAD_A(dst, ci, g)                                         \
    do {                                                           \
        const float4* p = pAf + (size_t)(ci) * 16 + (g) * 4;       \
        dst[0] = __ldg(p);                                         \
        dst[1] = __ldg(p + 1);                                     \
        dst[2] = __ldg(p + 2);                                     \
        dst[3] = __ldg(p + 3);                                     \
    } while (0)

// convert + store group g of chunk ci to its stage
#define STORE_A(src, ci, g)                                        \
    do {                                                           \
        const uint32_t d = sb + ((ci) & 1) * STAGEB + stA + (g) * 32; \
        uint4 w0 = pack8(src[0], src[1]);                          \
        uint4 w1 = pack8(src[2], src[3]);                          \
        asm volatile("st.shared.v4.b32 [%0], {%1,%2,%3,%4};"       \
            :: "r"(d), "r"(w0.x), "r"(w0.y), "r"(w0.z), "r"(w0.w) : "memory"); \
        asm volatile("st.shared.v4.b32 [%0], {%1,%2,%3,%4};"       \
            :: "r"(d + 16), "r"(w1.x), "r"(w1.y), "r"(w1.z), "r"(w1.w) : "memory"); \
    } while (0)

#define COMPUTE_KS(ks)                                                         \
    do {                                                                       \
        const uint32_t aoff = (uint32_t)((ks) * 32 + lm_colb);                 \
        uint32_t af[2][4], bf[4][4];                                           \
        _Pragma("unroll")                                                      \
        for (int t = 0; t < 2; t++)                                            \
            ldsm4(af[t], SA + (uint32_t)((m_off + t * 16 + lm_row) * ROWB) + aoff); \
        _Pragma("unroll")                                                      \
        for (int q = 0; q < 4; q++)                                            \
            ldsm4(bf[q], SB + (uint32_t)((n_off + q * 16 + lm_row) * ROWB) + aoff); \
        _Pragma("unroll")                                                      \
        for (int t = 0; t < 2; t++)                                            \
            _Pragma("unroll")                                                  \
            for (int n8 = 0; n8 < 8; n8++) {                                   \
                const int q = n8 >> 1, u = n8 & 1;                             \
                mma16816(acc[t][n8], af[t], bf[q][u], bf[q][u + 2]);           \
            }                                                                  \
    } while (0)

    // prologue: chunk 0 A in smem + B in flight
    {
        float4 a0[4], a1[4];
        LOAD_A(a0, 0, 0);
        LOAD_A(a1, 0, 1);
        ISSUE_B(0);
        STORE_A(a0, 0, 0);
        STORE_A(a1, 0, 1);
    }

    for (int i = 0; i < NCHUNK; ++i) {
        asm volatile("cp.async.wait_group 0;" ::: "memory");
        __syncthreads();

        const uint32_t SA = sb + (i & 1) * STAGEB;
        const uint32_t SB = SA + VERB;

        float4 ap[4];
        if (i + 1 < NCHUNK) {
            ISSUE_B(i + 1);
            LOAD_A(ap, i + 1, 0);
        }
        COMPUTE_KS(0);
        COMPUTE_KS(1);
        if (i + 1 < NCHUNK) {
            STORE_A(ap, i + 1, 0);
            LOAD_A(ap, i + 1, 1);
        }
        COMPUTE_KS(2);
        COMPUTE_KS(3);
        if (i + 1 < NCHUNK) {
            STORE_A(ap, i + 1, 1);
        }
    }

    float s0[2] = {0.f, 0.f}, s1[2] = {0.f, 0.f};
#pragma unroll
    for (int t = 0; t < 2; t++)
#pragma unroll
        for (int n8 = 0; n8 < 8; n8++) {
            const float w0 = wvsh[n_off + n8 * 8 + (lane & 3) * 2];
            const float w1 = wvsh[n_off + n8 * 8 + (lane & 3) * 2 + 1];
            s0[t] = fmaf(fast_tanh(acc[t][n8][0]), w0, s0[t]);
            s0[t] = fmaf(fast_tanh(acc[t][n8][1]), w1, s0[t]);
            s1[t] = fmaf(fast_tanh(acc[t][n8][2]), w0, s1[t]);
            s1[t] = fmaf(fast_tanh(acc[t][n8][3]), w1, s1[t]);
        }
#pragma unroll
    for (int o = 1; o <= 2; o <<= 1) {
#pragma unroll
        for (int t = 0; t < 2; t++) {
            s0[t] += __shfl_xor_sync(0xffffffffu, s0[t], o);
            s1[t] += __shfl_xor_sync(0xffffffffu, s1[t], o);
        }
    }
    __syncthreads();
    if ((lane & 3) == 0) {
        const int r = lane >> 2;
        float* rw = red + (wid >> 2) * 128;
        rw[m_off + r]          = s0[0];
        rw[m_off + r + 8]      = s1[0];
        rw[m_off + 16 + r]     = s0[1];
        rw[m_off + 16 + r + 8] = s1[1];
    }
    __syncthreads();
    if (tid < 128)
        part[ntile * Ntot + mtile * MT + tid] = red[tid] + red[128 + tid];
}

// ---------------------------------------------------------------------------
// fused softmax + split-r weighted sum (unchanged).
// ---------------------------------------------------------------------------
__global__ __launch_bounds__(256)
void wsum_sm(const float* __restrict__ part1, const float* __restrict__ img,
             const float* __restrict__ part2, const float* __restrict__ dns,
             float* __restrict__ vp, float* __restrict__ up)
{
    __shared__ float ws[SEQ];
    __shared__ float sh[8];
    const int b = blockIdx.x, y = blockIdx.y, t = threadIdx.x;

    const float* part; const float* X; float* outp;
    int r0, rn, n, N;
    if (y < VSPLIT) {
        part = part1; X = img; outp = vp + (size_t)y * BATCH * HID;
        r0 = y * (RIMG / VSPLIT); rn = RIMG / VSPLIT; n = RIMG; N = BATCH * RIMG;
    } else {
        const int s = y - VSPLIT;
        part = part2; X = dns; outp = up + (size_t)s * BATCH * HID;
        r0 = s * (SEQ / USPLIT); rn = SEQ / USPLIT; n = SEQ; N = BATCH * SEQ;
    }
    const int base = b * n;

    float m = -1e30f;
    for (int i = t; i < n; i += 256) {
        float x = 0.f;
#pragma unroll
        for (int c = 0; c < NCT; c++) x += part[c * N + base + i];
        ws[i] = x;
        m = fmaxf(m, x);
    }
    m = warpRedMax(m);
    if ((t & 31) == 0) sh[t >> 5] = m;
    __syncthreads();
    float M = sh[0];
#pragma unroll
    for (int q = 1; q < 8; q++) M = fmaxf(M, sh[q]);

    float sum = 0.f;
    for (int i = t; i < n; i += 256) {
        float e = expf(ws[i] - M);
        ws[i] = e;
        sum += e;
    }
    sum = warpRedSum(sum);
    __syncthreads();
    if ((t & 31) == 0) sh[t >> 5] = sum;
    __syncthreads();
    float S = 0.f;
#pragma unroll
    for (int q = 0; q < 8; q++) S += sh[q];
    const float inv = 1.f / S;
    __syncthreads();

    const float4* xb = (const float4*)(X + (size_t)b * n * HID) + (size_t)r0 * 256 + t;
    float4 acc = make_float4(0.f, 0.f, 0.f, 0.f);
#pragma unroll 4
    for (int r = 0; r < rn; r++) {
        const float wr = ws[r0 + r];
        const float4 x = __ldg(&xb[(size_t)r * 256]);
        acc.x = fmaf(wr, x.x, acc.x);
        acc.y = fmaf(wr, x.y, acc.y);
        acc.z = fmaf(wr, x.z, acc.z);
        acc.w = fmaf(wr, x.w, acc.w);
    }
    acc.x *= inv; acc.y *= inv; acc.z *= inv; acc.w *= inv;
    ((float4*)(outp + b * HID))[t] = acc;
}

// ---------------------------------------------------------------------------
// finalize: reduce partials -> u,v in regs, broadcast over s-range.
// ---------------------------------------------------------------------------
#define NSC 16
#define SCHUNK (SEQ / NSC)    // 32
__global__ __launch_bounds__(256)
void finalize(const float* __restrict__ vp, const float* __restrict__ up,
              float4* __restrict__ out)
{
    const int b = blockIdx.x, sc = blockIdx.y, t = threadIdx.x;

    float4 sv = make_float4(0.f, 0.f, 0.f, 0.f);
#pragma unroll
    for (int s = 0; s < VSPLIT; s++) {
        float4 x = __ldg(((const float4*)(vp + (size_t)s * BATCH * HID + b * HID)) + t);
        sv.x += x.x; sv.y += x.y; sv.z += x.z; sv.w += x.w;
    }
    float4 su = make_float4(0.f, 0.f, 0.f, 0.f);
#pragma unroll
    for (int s = 0; s < USPLIT; s++) {
        float4 x = __ldg(((const float4*)(up + (size_t)s * BATCH * HID + b * HID)) + t);
        su.x += x.x; su.y += x.y; su.z += x.z; su.w += x.w;
    }

    float4* ou = out + ((size_t)b * SEQ + sc * SCHUNK) * 256 + t;
    float4* ov = ou + (size_t)BATCH * SEQ * 256;
#pragma unroll 4
    for (int s = 0; s < SCHUNK; s++) {
        ou[(size_t)s * 256] = su;
        ov[(size_t)s * 256] = sv;
    }
}

// ---------------------------------------------------------------------------
extern "C" void kernel_launch(void* const* d_in, const int* in_sizes, int n_in,
                              void* d_out, int out_size)
{
    const float* dns    = (const float*)d_in[0];
    const float* img    = (const float*)d_in[1];
    const float* W_i1   = (const float*)d_in[4];
    const float* w_att1 = (const float*)d_in[5];
    const float* W_d2   = (const float*)d_in[7];
    const float* w_att2 = (const float*)d_in[10];
    float* out = (float*)d_out;

    float *part1, *part2, *vp, *up;
    cudaGetSymbolAddress((void**)&part1, g_part1);
    cudaGetSymbolAddress((void**)&part2, g_part2);
    cudaGetSymbolAddress((void**)&vp, g_vp);
    cudaGetSymbolAddress((void**)&up, g_up);

    __half *wi_h, *wd_h;
    cudaGetSymbolAddress((void**)&wi_h, g_wi_h);
    cudaGetSymbolAddress((void**)&wd_h, g_wd_h);

    cudaFuncSetAttribute(gemm_h2, cudaFuncAttributeMaxDynamicSharedMemorySize, SMEM_DYN);

    tohalf2<<<2 * NB_W, 256>>>(W_i1, wi_h, W_d2, wd_h);

    gemm_h2<<<dim3(NCT, DNS_MT + IMG_MT), 256, SMEM_DYN>>>(
        dns, wd_h, w_att2 + HID, part2,
        img, wi_h, w_att1 + HID, part1);

    wsum_sm<<<dim3(BATCH, VSPLIT + USPLIT), 256>>>(part1, img, part2, dns, vp, up);

    finalize<<<dim3(BATCH, NSC), 256>>>(vp, up, (float4*)out);
}

// round 14
// speedup vs baseline: 1.1200x; 1.1200x over previous
#include <cuda_runtime.h>
#include <cuda_fp16.h>
#include <math.h>
#include <stdint.h>

#define HID   1024
#define SEQ   512
#define RIMG  196
#define BATCH 32
#define NCT   8
#define MT    128
#define NT    128
#define KC    64
#define NCHUNK (HID / KC)
#define ROWB  144
#define VERB  (128 * ROWB)
#define STAGEB (2 * VERB)
#define NSTAGE 3
#define WV_OFF  (NSTAGE * STAGEB)      // 110592
#define RED_OFF (WV_OFF + 512)
#define SMEM_DYN (RED_OFF + 1024 + 256)

#define IMG_MT (BATCH * RIMG / MT)    // 49
#define DNS_MT (BATCH * SEQ / MT)     // 128

#define VSPLIT 7
#define USPLIT 16

// ---------------- scratch ----------------
__device__ float g_part1[NCT * BATCH * RIMG];
__device__ float g_part2[NCT * BATCH * SEQ];
__device__ float g_vp[VSPLIT * BATCH * HID];
__device__ float g_up[USPLIT * BATCH * HID];

__device__ __half g_dns_h[BATCH * SEQ * HID];
__device__ __half g_img_h[BATCH * RIMG * HID];
__device__ __half g_wi_h[HID * HID];
__device__ __half g_wd_h[HID * HID];

// ---------------- helpers ----------------
__device__ __forceinline__ uint32_t smem_u32(const void* p) {
    uint32_t a;
    asm("{ .reg .u64 t; cvta.to.shared.u64 t, %1; cvt.u32.u64 %0, t; }" : "=r"(a) : "l"(p));
    return a;
}
__device__ __forceinline__ void ldsm4(uint32_t* r, uint32_t addr) {
    asm volatile("ldmatrix.sync.aligned.m8n8.x4.shared.b16 {%0,%1,%2,%3}, [%4];"
                 : "=r"(r[0]), "=r"(r[1]), "=r"(r[2]), "=r"(r[3]) : "r"(addr));
}
__device__ __forceinline__ void mma16816(float* c, const uint32_t* a,
                                         uint32_t b0, uint32_t b1) {
    asm volatile(
        "mma.sync.aligned.m16n8k16.row.col.f32.f16.f16.f32 "
        "{%0,%1,%2,%3}, {%4,%5,%6,%7}, {%8,%9}, {%0,%1,%2,%3};"
        : "+f"(c[0]), "+f"(c[1]), "+f"(c[2]), "+f"(c[3])
        : "r"(a[0]), "r"(a[1]), "r"(a[2]), "r"(a[3]), "r"(b0), "r"(b1));
}
#define CP16(s, g) \
    asm volatile("cp.async.cg.shared.global [%0], [%1], 16;" :: "r"(s), "l"(g) : "memory")
#define CP_COMMIT() asm volatile("cp.async.commit_group;" ::: "memory")

__device__ __forceinline__ float fast_tanh(float x) {
    return 1.f - 2.f / (__expf(2.f * x) + 1.f);
}
__device__ __forceinline__ float warpRedMax(float v) {
#pragma unroll
    for (int o = 16; o > 0; o >>= 1) v = fmaxf(v, __shfl_xor_sync(0xffffffffu, v, o));
    return v;
}
__device__ __forceinline__ float warpRedSum(float v) {
#pragma unroll
    for (int o = 16; o > 0; o >>= 1) v += __shfl_xor_sync(0xffffffffu, v, o);
    return v;
}

// ---------------------------------------------------------------------------
// fused fp32->fp16 convert, 16 floats/thread (MLP 4) — all four tensors
// ---------------------------------------------------------------------------
#define NB_DNS (BATCH * SEQ * HID / 4096)    // 4096
#define NB_IMG (BATCH * RIMG * HID / 4096)   // 1568
#define NB_W   (HID * HID / 4096)            // 256
__global__ __launch_bounds__(256)
void tohalf4(const float* __restrict__ i0, __half* __restrict__ o0,
             const float* __restrict__ i1, __half* __restrict__ o1,
             const float* __restrict__ i2, __half* __restrict__ o2,
             const float* __restrict__ i3, __half* __restrict__ o3)
{
    const int b = blockIdx.x;
    const float* in; __half* out; int base;
    if (b < NB_DNS)                       { in = i0; out = o0; base = b; }
    else if (b < NB_DNS + NB_IMG)         { in = i1; out = o1; base = b - NB_DNS; }
    else if (b < NB_DNS + NB_IMG + NB_W)  { in = i2; out = o2; base = b - NB_DNS - NB_IMG; }
    else                                  { in = i3; out = o3; base = b - NB_DNS - NB_IMG - NB_W; }
    const int i = base * 256 + threadIdx.x;
    const float4* p = (const float4*)in + (size_t)i * 4;
    float4 f[4];
#pragma unroll
    for (int j = 0; j < 4; j++) f[j] = __ldg(p + j);
    uint4* o = (uint4*)out + (size_t)i * 2;
#pragma unroll
    for (int g = 0; g < 2; g++) {
        float4 a = f[g * 2], c = f[g * 2 + 1];
        __half2 h0 = __floats2half2_rn(a.x, a.y);
        __half2 h1 = __floats2half2_rn(a.z, a.w);
        __half2 h2 = __floats2half2_rn(c.x, c.y);
        __half2 h3 = __floats2half2_rn(c.z, c.w);
        uint4 w;
        w.x = *reinterpret_cast<uint32_t*>(&h0);
        w.y = *reinterpret_cast<uint32_t*>(&h1);
        w.z = *reinterpret_cast<uint32_t*>(&h2);
        w.w = *reinterpret_cast<uint32_t*>(&h3);
        o[g] = w;
    }
}

// ---------------------------------------------------------------------------
// fused single-launch fp16 GEMM for BOTH score paths; 3-stage cp.async.
// ---------------------------------------------------------------------------
__global__ __launch_bounds__(256, 2)
void gemm_h2(const __half* __restrict__ Xd, const __half* __restrict__ Wd,
             const float* __restrict__ wvd, float* __restrict__ partd,
             const __half* __restrict__ Xi, const __half* __restrict__ Wi,
             const float* __restrict__ wvi, float* __restrict__ parti)
{
    extern __shared__ char smem[];
    const uint32_t sb = smem_u32(smem);
    const int tid = threadIdx.x, lane = tid & 31, wid = tid >> 5;
    const int ntile = blockIdx.x;

    const __half *X, *W;
    const float* wvec;
    float* part;
    int mtile, Ntot;
    if (blockIdx.y < DNS_MT) {
        X = Xd; W = Wd; wvec = wvd; part = partd;
        mtile = blockIdx.y; Ntot = BATCH * SEQ;
    } else {
        X = Xi; W = Wi; wvec = wvi; part = parti;
        mtile = blockIdx.y - DNS_MT; Ntot = BATCH * RIMG;
    }

    float* wvsh = (float*)(smem + WV_OFF);
    float* red  = (float*)(smem + RED_OFF);
    if (tid < 128) wvsh[tid] = wvec[ntile * NT + tid];

    const int row  = tid >> 1;
    const int half = tid & 1;
    const char* pA = (const char*)(X + (size_t)(mtile * MT + row) * HID) + half * 64;
    const char* pB = (const char*)(W + (size_t)(ntile * NT + row) * HID) + half * 64;
    const uint32_t st = (uint32_t)(row * ROWB + half * 64);

    const int m_off = (wid & 3) * 32;
    const int n_off = (wid >> 2) * 64;
    const int lm_row  = lane & 15;
    const int lm_colb = (lane & 16) ? 16 : 0;

    float acc[2][8][4];
#pragma unroll
    for (int t = 0; t < 2; t++)
#pragma unroll
        for (int n = 0; n < 8; n++)
#pragma unroll
            for (int j = 0; j < 4; j++) acc[t][n][j] = 0.f;

#define ISSUE(ci)                                                  \
    do {                                                           \
        const uint32_t s0 = sb + ((ci) % NSTAGE) * STAGEB + st;    \
        const char* gA = pA + (size_t)(ci) * 128;                  \
        const char* gB = pB + (size_t)(ci) * 128;                  \
        CP16(s0,      gA);                                         \
        CP16(s0 + 16, gA + 16);                                    \
        CP16(s0 + 32, gA + 32);                                    \
        CP16(s0 + 48, gA + 48);                                    \
        CP16(s0 + VERB,      gB);                                  \
        CP16(s0 + VERB + 16, gB + 16);                             \
        CP16(s0 + VERB + 32, gB + 32);                             \
        CP16(s0 + VERB + 48, gB + 48);                             \
        CP_COMMIT();                                               \
    } while (0)

    ISSUE(0);
    ISSUE(1);

    for (int i = 0; i < NCHUNK; ++i) {
        if (i + 1 < NCHUNK)
            asm volatile("cp.async.wait_group 1;" ::: "memory");
        else
            asm volatile("cp.async.wait_group 0;" ::: "memory");
        __syncthreads();
        if (i + 2 < NCHUNK) ISSUE(i + 2);

        const uint32_t SA = sb + (i % NSTAGE) * STAGEB;
        const uint32_t SB = SA + VERB;
#pragma unroll
        for (int ks = 0; ks < 4; ks++) {
            const uint32_t aoff = (uint32_t)(ks * 32 + lm_colb);
            uint32_t af[2][4], bf[4][4];
#pragma unroll
            for (int t = 0; t < 2; t++)
                ldsm4(af[t], SA + (uint32_t)((m_off + t * 16 + lm_row) * ROWB) + aoff);
#pragma unroll
            for (int q = 0; q < 4; q++)
                ldsm4(bf[q], SB + (uint32_t)((n_off + q * 16 + lm_row) * ROWB) + aoff);
#pragma unroll
            for (int t = 0; t < 2; t++)
#pragma unroll
                for (int n8 = 0; n8 < 8; n8++) {
                    const int q = n8 >> 1, u = n8 & 1;
                    mma16816(acc[t][n8], af[t], bf[q][u], bf[q][u + 2]);
                }
        }
    }

    float s0[2] = {0.f, 0.f}, s1[2] = {0.f, 0.f};
#pragma unroll
    for (int t = 0; t < 2; t++)
#pragma unroll
        for (int n8 = 0; n8 < 8; n8++) {
            const float w0 = wvsh[n_off + n8 * 8 + (lane & 3) * 2];
            const float w1 = wvsh[n_off + n8 * 8 + (lane & 3) * 2 + 1];
            s0[t] = fmaf(fast_tanh(acc[t][n8][0]), w0, s0[t]);
            s0[t] = fmaf(fast_tanh(acc[t][n8][1]), w1, s0[t]);
            s1[t] = fmaf(fast_tanh(acc[t][n8][2]), w0, s1[t]);
            s1[t] = fmaf(fast_tanh(acc[t][n8][3]), w1, s1[t]);
        }
#pragma unroll
    for (int o = 1; o <= 2; o <<= 1) {
#pragma unroll
        for (int t = 0; t < 2; t++) {
            s0[t] += __shfl_xor_sync(0xffffffffu, s0[t], o);
            s1[t] += __shfl_xor_sync(0xffffffffu, s1[t], o);
        }
    }
    __syncthreads();
    if ((lane & 3) == 0) {
        const int r = lane >> 2;
        float* rw = red + (wid >> 2) * 128;
        rw[m_off + r]          = s0[0];
        rw[m_off + r + 8]      = s1[0];
        rw[m_off + 16 + r]     = s0[1];
        rw[m_off + 16 + r + 8] = s1[1];
    }
    __syncthreads();
    if (tid < 128)
        part[ntile * Ntot + mtile * MT + tid] = red[tid] + red[128 + tid];
}

// ---------------------------------------------------------------------------
// fused softmax + split-r weighted sum (unchanged).
// ---------------------------------------------------------------------------
__global__ __launch_bounds__(256)
void wsum_sm(const float* __restrict__ part1, const float* __restrict__ img,
             const float* __restrict__ part2, const float* __restrict__ dns,
             float* __restrict__ vp, float* __restrict__ up)
{
    __shared__ float ws[SEQ];
    __shared__ float sh[8];
    const int b = blockIdx.x, y = blockIdx.y, t = threadIdx.x;

    const float* part; const float* X; float* outp;
    int r0, rn, n, N;
    if (y < VSPLIT) {
        part = part1; X = img; outp = vp + (size_t)y * BATCH * HID;
        r0 = y * (RIMG / VSPLIT); rn = RIMG / VSPLIT; n = RIMG; N = BATCH * RIMG;
    } else {
        const int s = y - VSPLIT;
        part = part2; X = dns; outp = up + (size_t)s * BATCH * HID;
        r0 = s * (SEQ / USPLIT); rn = SEQ / USPLIT; n = SEQ; N = BATCH * SEQ;
    }
    const int base = b * n;

    float m = -1e30f;
    for (int i = t; i < n; i += 256) {
        float x = 0.f;
#pragma unroll
        for (int c = 0; c < NCT; c++) x += part[c * N + base + i];
        ws[i] = x;
        m = fmaxf(m, x);
    }
    m = warpRedMax(m);
    if ((t & 31) == 0) sh[t >> 5] = m;
    __syncthreads();
    float M = sh[0];
#pragma unroll
    for (int q = 1; q < 8; q++) M = fmaxf(M, sh[q]);

    float sum = 0.f;
    for (int i = t; i < n; i += 256) {
        float e = expf(ws[i] - M);
        ws[i] = e;
        sum += e;
    }
    sum = warpRedSum(sum);
    __syncthreads();
    if ((t & 31) == 0) sh[t >> 5] = sum;
    __syncthreads();
    float S = 0.f;
#pragma unroll
    for (int q = 0; q < 8; q++) S += sh[q];
    const float inv = 1.f / S;
    __syncthreads();

    const float4* xb = (const float4*)(X + (size_t)b * n * HID) + (size_t)r0 * 256 + t;
    float4 acc = make_float4(0.f, 0.f, 0.f, 0.f);
#pragma unroll 4
    for (int r = 0; r < rn; r++) {
        const float wr = ws[r0 + r];
        const float4 x = __ldg(&xb[(size_t)r * 256]);
        acc.x = fmaf(wr, x.x, acc.x);
        acc.y = fmaf(wr, x.y, acc.y);
        acc.z = fmaf(wr, x.z, acc.z);
        acc.w = fmaf(wr, x.w, acc.w);
    }
    acc.x *= inv; acc.y *= inv; acc.z *= inv; acc.w *= inv;
    ((float4*)(outp + b * HID))[t] = acc;
}

// ---------------------------------------------------------------------------
// finalize: reduce partials -> u,v in regs, broadcast over s-range.
// ---------------------------------------------------------------------------
#define NSC 8
#define SCHUNK (SEQ / NSC)    // 64
__global__ __launch_bounds__(256)
void finalize(const float* __restrict__ vp, const float* __restrict__ up,
              float4* __restrict__ out)
{
    const int b = blockIdx.x, sc = blockIdx.y, t = threadIdx.x;

    float4 sv = make_float4(0.f, 0.f, 0.f, 0.f);
#pragma unroll
    for (int s = 0; s < VSPLIT; s++) {
        float4 x = __ldg(((const float4*)(vp + (size_t)s * BATCH * HID + b * HID)) + t);
        sv.x += x.x; sv.y += x.y; sv.z += x.z; sv.w += x.w;
    }
    float4 su = make_float4(0.f, 0.f, 0.f, 0.f);
#pragma unroll
    for (int s = 0; s < USPLIT; s++) {
        float4 x = __ldg(((const float4*)(up + (size_t)s * BATCH * HID + b * HID)) + t);
        su.x += x.x; su.y += x.y; su.z += x.z; su.w += x.w;
    }

    float4* ou = out + ((size_t)b * SEQ + sc * SCHUNK) * 256 + t;
    float4* ov = ou + (size_t)BATCH * SEQ * 256;
#pragma unroll 4
    for (int s = 0; s < SCHUNK; s++) {
        ou[(size_t)s * 256] = su;
        ov[(size_t)s * 256] = sv;
    }
}

// ---------------------------------------------------------------------------
extern "C" void kernel_launch(void* const* d_in, const int* in_sizes, int n_in,
                              void* d_out, int out_size)
{
    const float* dns    = (const float*)d_in[0];
    const float* img    = (const float*)d_in[1];
    const float* W_i1   = (const float*)d_in[4];
    const float* w_att1 = (const float*)d_in[5];
    const float* W_d2   = (const float*)d_in[7];
    const float* w_att2 = (const float*)d_in[10];
    float* out = (float*)d_out;

    float *part1, *part2, *vp, *up;
    cudaGetSymbolAddress((void**)&part1, g_part1);
    cudaGetSymbolAddress((void**)&part2, g_part2);
    cudaGetSymbolAddress((void**)&vp, g_vp);
    cudaGetSymbolAddress((void**)&up, g_up);

    __half *dns_h, *img_h, *wi_h, *wd_h;
    cudaGetSymbolAddress((void**)&dns_h, g_dns_h);
    cudaGetSymbolAddress((void**)&img_h, g_img_h);
    cudaGetSymbolAddress((void**)&wi_h, g_wi_h);
    cudaGetSymbolAddress((void**)&wd_h, g_wd_h);

    cudaFuncSetAttribute(gemm_h2, cudaFuncAttributeMaxDynamicSharedMemorySize, SMEM_DYN);

    tohalf4<<<NB_DNS + NB_IMG + 2 * NB_W, 256>>>(dns, dns_h, img, img_h,
                                                 W_i1, wi_h, W_d2, wd_h);

    gemm_h2<<<dim3(NCT, DNS_MT + IMG_MT), 256, SMEM_DYN>>>(
        dns_h, wd_h, w_att2 + HID, part2,
        img_h, wi_h, w_att1 + HID, part1);

    wsum_sm<<<dim3(BATCH, VSPLIT + USPLIT), 256>>>(part1, img, part2, dns, vp, up);

    finalize<<<dim3(BATCH, NSC), 256>>>(vp, up, (float4*)out);
}

// round 15
// speedup vs baseline: 1.1850x; 1.0580x over previous
#include <cuda_runtime.h>
#include <cuda_fp16.h>
#include <math.h>
#include <stdint.h>

#define HID   1024
#define SEQ   512
#define RIMG  196
#define BATCH 32
#define NCT   8
#define MT    128
#define NT    128
#define KC    64
#define NCHUNK (HID / KC)
#define ROWB  144
#define VERB  (128 * ROWB)
#define STAGEB (2 * VERB)
#define WV_OFF  (2 * STAGEB)
#define RED_OFF (WV_OFF + 512)
#define SMEM_DYN (RED_OFF + 1024 + 256)

#define IMG_MT (BATCH * RIMG / MT)    // 49
#define DNS_MT (BATCH * SEQ / MT)     // 128

#define VSPLIT 7
#define USPLIT 16

// ---------------- scratch ----------------
__device__ float g_part1[NCT * BATCH * RIMG];
__device__ float g_part2[NCT * BATCH * SEQ];
__device__ float g_vp[VSPLIT * BATCH * HID];
__device__ float g_up[USPLIT * BATCH * HID];

__device__ __half g_dns_h[BATCH * SEQ * HID];
__device__ __half g_img_h[BATCH * RIMG * HID];
__device__ __half g_wi_h[HID * HID];
__device__ __half g_wd_h[HID * HID];

// ---------------- helpers ----------------
__device__ __forceinline__ uint32_t smem_u32(const void* p) {
    uint32_t a;
    asm("{ .reg .u64 t; cvta.to.shared.u64 t, %1; cvt.u32.u64 %0, t; }" : "=r"(a) : "l"(p));
    return a;
}
__device__ __forceinline__ void ldsm4(uint32_t* r, uint32_t addr) {
    asm volatile("ldmatrix.sync.aligned.m8n8.x4.shared.b16 {%0,%1,%2,%3}, [%4];"
                 : "=r"(r[0]), "=r"(r[1]), "=r"(r[2]), "=r"(r[3]) : "r"(addr));
}
__device__ __forceinline__ void mma16816(float* c, const uint32_t* a,
                                         uint32_t b0, uint32_t b1) {
    asm volatile(
        "mma.sync.aligned.m16n8k16.row.col.f32.f16.f16.f32 "
        "{%0,%1,%2,%3}, {%4,%5,%6,%7}, {%8,%9}, {%0,%1,%2,%3};"
        : "+f"(c[0]), "+f"(c[1]), "+f"(c[2]), "+f"(c[3])
        : "r"(a[0]), "r"(a[1]), "r"(a[2]), "r"(a[3]), "r"(b0), "r"(b1));
}
#define CP16(s, g) \
    asm volatile("cp.async.cg.shared.global [%0], [%1], 16;" :: "r"(s), "l"(g) : "memory")
#define CP_COMMIT() asm volatile("cp.async.commit_group;" ::: "memory")

__device__ __forceinline__ float fast_tanh(float x) {
    return 1.f - 2.f / (__expf(2.f * x) + 1.f);
}
__device__ __forceinline__ float warpRedMax(float v) {
#pragma unroll
    for (int o = 16; o > 0; o >>= 1) v = fmaxf(v, __shfl_xor_sync(0xffffffffu, v, o));
    return v;
}
__device__ __forceinline__ float warpRedSum(float v) {
#pragma unroll
    for (int o = 16; o > 0; o >>= 1) v += __shfl_xor_sync(0xffffffffu, v, o);
    return v;
}

// ---------------------------------------------------------------------------
// fused fp32->fp16 convert, 16 floats/thread (MLP 4) — all four tensors
// ---------------------------------------------------------------------------
#define NB_DNS (BATCH * SEQ * HID / 4096)    // 4096
#define NB_IMG (BATCH * RIMG * HID / 4096)   // 1568
#define NB_W   (HID * HID / 4096)            // 256
__global__ __launch_bounds__(256)
void tohalf4(const float* __restrict__ i0, __half* __restrict__ o0,
             const float* __restrict__ i1, __half* __restrict__ o1,
             const float* __restrict__ i2, __half* __restrict__ o2,
             const float* __restrict__ i3, __half* __restrict__ o3)
{
    const int b = blockIdx.x;
    const float* in; __half* out; int base;
    if (b < NB_DNS)                       { in = i0; out = o0; base = b; }
    else if (b < NB_DNS + NB_IMG)         { in = i1; out = o1; base = b - NB_DNS; }
    else if (b < NB_DNS + NB_IMG + NB_W)  { in = i2; out = o2; base = b - NB_DNS - NB_IMG; }
    else                                  { in = i3; out = o3; base = b - NB_DNS - NB_IMG - NB_W; }
    const int i = base * 256 + threadIdx.x;
    const float4* p = (const float4*)in + (size_t)i * 4;
    float4 f[4];
#pragma unroll
    for (int j = 0; j < 4; j++) f[j] = __ldg(p + j);
    uint4* o = (uint4*)out + (size_t)i * 2;
#pragma unroll
    for (int g = 0; g < 2; g++) {
        float4 a = f[g * 2], c = f[g * 2 + 1];
        __half2 h0 = __floats2half2_rn(a.x, a.y);
        __half2 h1 = __floats2half2_rn(a.z, a.w);
        __half2 h2 = __floats2half2_rn(c.x, c.y);
        __half2 h3 = __floats2half2_rn(c.z, c.w);
        uint4 w;
        w.x = *reinterpret_cast<uint32_t*>(&h0);
        w.y = *reinterpret_cast<uint32_t*>(&h1);
        w.z = *reinterpret_cast<uint32_t*>(&h2);
        w.w = *reinterpret_cast<uint32_t*>(&h3);
        o[g] = w;
    }
}

// ---------------------------------------------------------------------------
// fused single-launch fp16 GEMM for BOTH score paths (R12 proven version).
// ---------------------------------------------------------------------------
__global__ __launch_bounds__(256, 2)
void gemm_h2(const __half* __restrict__ Xd, const __half* __restrict__ Wd,
             const float* __restrict__ wvd, float* __restrict__ partd,
             const __half* __restrict__ Xi, const __half* __restrict__ Wi,
             const float* __restrict__ wvi, float* __restrict__ parti)
{
    extern __shared__ char smem[];
    const uint32_t sb = smem_u32(smem);
    const int tid = threadIdx.x, lane = tid & 31, wid = tid >> 5;
    const int ntile = blockIdx.x;

    const __half *X, *W;
    const float* wvec;
    float* part;
    int mtile, Ntot;
    if (blockIdx.y < DNS_MT) {
        X = Xd; W = Wd; wvec = wvd; part = partd;
        mtile = blockIdx.y; Ntot = BATCH * SEQ;
    } else {
        X = Xi; W = Wi; wvec = wvi; part = parti;
        mtile = blockIdx.y - DNS_MT; Ntot = BATCH * RIMG;
    }

    float* wvsh = (float*)(smem + WV_OFF);
    float* red  = (float*)(smem + RED_OFF);
    if (tid < 128) wvsh[tid] = wvec[ntile * NT + tid];

    const int row  = tid >> 1;
    const int half = tid & 1;
    const char* pA = (const char*)(X + (size_t)(mtile * MT + row) * HID) + half * 64;
    const char* pB = (const char*)(W + (size_t)(ntile * NT + row) * HID) + half * 64;
    const uint32_t st = (uint32_t)(row * ROWB + half * 64);

    const int m_off = (wid & 3) * 32;
    const int n_off = (wid >> 2) * 64;
    const int lm_row  = lane & 15;
    const int lm_colb = (lane & 16) ? 16 : 0;

    float acc[2][8][4];
#pragma unroll
    for (int t = 0; t < 2; t++)
#pragma unroll
        for (int n = 0; n < 8; n++)
#pragma unroll
            for (int j = 0; j < 4; j++) acc[t][n][j] = 0.f;

#define ISSUE(ci)                                                  \
    do {                                                           \
        const uint32_t s0 = sb + ((ci) & 1) * STAGEB + st;         \
        const char* gA = pA + (size_t)(ci) * 128;                  \
        const char* gB = pB + (size_t)(ci) * 128;                  \
        CP16(s0,      gA);                                         \
        CP16(s0 + 16, gA + 16);                                    \
        CP16(s0 + 32, gA + 32);                                    \
        CP16(s0 + 48, gA + 48);                                    \
        CP16(s0 + VERB,      gB);                                  \
        CP16(s0 + VERB + 16, gB + 16);                             \
        CP16(s0 + VERB + 32, gB + 32);                             \
        CP16(s0 + VERB + 48, gB + 48);                             \
        CP_COMMIT();                                               \
    } while (0)

    ISSUE(0);

    for (int i = 0; i < NCHUNK; ++i) {
        asm volatile("cp.async.wait_group 0;" ::: "memory");
        __syncthreads();
        if (i + 1 < NCHUNK) ISSUE(i + 1);

        const uint32_t SA = sb + (i & 1) * STAGEB;
        const uint32_t SB = SA + VERB;
#pragma unroll
        for (int ks = 0; ks < 4; ks++) {
            const uint32_t aoff = (uint32_t)(ks * 32 + lm_colb);
            uint32_t af[2][4], bf[4][4];
#pragma unroll
            for (int t = 0; t < 2; t++)
                ldsm4(af[t], SA + (uint32_t)((m_off + t * 16 + lm_row) * ROWB) + aoff);
#pragma unroll
            for (int q = 0; q < 4; q++)
                ldsm4(bf[q], SB + (uint32_t)((n_off + q * 16 + lm_row) * ROWB) + aoff);
#pragma unroll
            for (int t = 0; t < 2; t++)
#pragma unroll
                for (int n8 = 0; n8 < 8; n8++) {
                    const int q = n8 >> 1, u = n8 & 1;
                    mma16816(acc[t][n8], af[t], bf[q][u], bf[q][u + 2]);
                }
        }
    }

    float s0[2] = {0.f, 0.f}, s1[2] = {0.f, 0.f};
#pragma unroll
    for (int t = 0; t < 2; t++)
#pragma unroll
        for (int n8 = 0; n8 < 8; n8++) {
            const float w0 = wvsh[n_off + n8 * 8 + (lane & 3) * 2];
            const float w1 = wvsh[n_off + n8 * 8 + (lane & 3) * 2 + 1];
            s0[t] = fmaf(fast_tanh(acc[t][n8][0]), w0, s0[t]);
            s0[t] = fmaf(fast_tanh(acc[t][n8][1]), w1, s0[t]);
            s1[t] = fmaf(fast_tanh(acc[t][n8][2]), w0, s1[t]);
            s1[t] = fmaf(fast_tanh(acc[t][n8][3]), w1, s1[t]);
        }
#pragma unroll
    for (int o = 1; o <= 2; o <<= 1) {
#pragma unroll
        for (int t = 0; t < 2; t++) {
            s0[t] += __shfl_xor_sync(0xffffffffu, s0[t], o);
            s1[t] += __shfl_xor_sync(0xffffffffu, s1[t], o);
        }
    }
    __syncthreads();
    if ((lane & 3) == 0) {
        const int r = lane >> 2;
        float* rw = red + (wid >> 2) * 128;
        rw[m_off + r]          = s0[0];
        rw[m_off + r + 8]      = s1[0];
        rw[m_off + 16 + r]     = s0[1];
        rw[m_off + 16 + r + 8] = s1[1];
    }
    __syncthreads();
    if (tid < 128)
        part[ntile * Ntot + mtile * MT + tid] = red[tid] + red[128 + tid];
}

// ---------------------------------------------------------------------------
// fused softmax + split-r weighted sum, reading the fp16 copies.
// thread t covers h = t*4..t*4+3 (4 halves = 8B load per r).
// ---------------------------------------------------------------------------
__global__ __launch_bounds__(256)
void wsum_sm(const float* __restrict__ part1, const __half* __restrict__ imgh,
             const float* __restrict__ part2, const __half* __restrict__ dnsh,
             float* __restrict__ vp, float* __restrict__ up)
{
    __shared__ float ws[SEQ];
    __shared__ float sh[8];
    const int b = blockIdx.x, y = blockIdx.y, t = threadIdx.x;

    const float* part; const __half* X; float* outp;
    int r0, rn, n, N;
    if (y < VSPLIT) {
        part = part1; X = imgh; outp = vp + (size_t)y * BATCH * HID;
        r0 = y * (RIMG / VSPLIT); rn = RIMG / VSPLIT; n = RIMG; N = BATCH * RIMG;
    } else {
        const int s = y - VSPLIT;
        part = part2; X = dnsh; outp = up + (size_t)s * BATCH * HID;
        r0 = s * (SEQ / USPLIT); rn = SEQ / USPLIT; n = SEQ; N = BATCH * SEQ;
    }
    const int base = b * n;

    float m = -1e30f;
    for (int i = t; i < n; i += 256) {
        float x = 0.f;
#pragma unroll
        for (int c = 0; c < NCT; c++) x += part[c * N + base + i];
        ws[i] = x;
        m = fmaxf(m, x);
    }
    m = warpRedMax(m);
    if ((t & 31) == 0) sh[t >> 5] = m;
    __syncthreads();
    float M = sh[0];
#pragma unroll
    for (int q = 1; q < 8; q++) M = fmaxf(M, sh[q]);

    float sum = 0.f;
    for (int i = t; i < n; i += 256) {
        float e = expf(ws[i] - M);
        ws[i] = e;
        sum += e;
    }
    sum = warpRedSum(sum);
    __syncthreads();
    if ((t & 31) == 0) sh[t >> 5] = sum;
    __syncthreads();
    float S = 0.f;
#pragma unroll
    for (int q = 0; q < 8; q++) S += sh[q];
    const float inv = 1.f / S;
    __syncthreads();

    // weighted sum over r-chunk; uint2 = 4 halves per r per thread
    const uint2* xb = (const uint2*)(X + (size_t)b * n * HID) + (size_t)r0 * 256 + t;
    float4 acc = make_float4(0.f, 0.f, 0.f, 0.f);
#pragma unroll 4
    for (int r = 0; r < rn; r++) {
        const float wr = ws[r0 + r];
        const uint2 h4 = __ldg(&xb[(size_t)r * 256]);
        const __half2 hA = *reinterpret_cast<const __half2*>(&h4.x);
        const __half2 hB = *reinterpret_cast<const __half2*>(&h4.y);
        const float2 fA = __half22float2(hA);
        const float2 fB = __half22float2(hB);
        acc.x = fmaf(wr, fA.x, acc.x);
        acc.y = fmaf(wr, fA.y, acc.y);
        acc.z = fmaf(wr, fB.x, acc.z);
        acc.w = fmaf(wr, fB.y, acc.w);
    }
    acc.x *= inv; acc.y *= inv; acc.z *= inv; acc.w *= inv;
    ((float4*)(outp + b * HID))[t] = acc;
}

// ---------------------------------------------------------------------------
// finalize: reduce partials -> u,v in regs, broadcast over s-range.
// ---------------------------------------------------------------------------
#define NSC 8
#define SCHUNK (SEQ / NSC)    // 64
__global__ __launch_bounds__(256)
void finalize(const float* __restrict__ vp, const float* __restrict__ up,
              float4* __restrict__ out)
{
    const int b = blockIdx.x, sc = blockIdx.y, t = threadIdx.x;

    float4 sv = make_float4(0.f, 0.f, 0.f, 0.f);
#pragma unroll
    for (int s = 0; s < VSPLIT; s++) {
        float4 x = __ldg(((const float4*)(vp + (size_t)s * BATCH * HID + b * HID)) + t);
        sv.x += x.x; sv.y += x.y; sv.z += x.z; sv.w += x.w;
    }
    float4 su = make_float4(0.f, 0.f, 0.f, 0.f);
#pragma unroll
    for (int s = 0; s < USPLIT; s++) {
        float4 x = __ldg(((const float4*)(up + (size_t)s * BATCH * HID + b * HID)) + t);
        su.x += x.x; su.y += x.y; su.z += x.z; su.w += x.w;
    }

    float4* ou = out + ((size_t)b * SEQ + sc * SCHUNK) * 256 + t;
    float4* ov = ou + (size_t)BATCH * SEQ * 256;
#pragma unroll 4
    for (int s = 0; s < SCHUNK; s++) {
        ou[(size_t)s * 256] = su;
        ov[(size_t)s * 256] = sv;
    }
}

// ---------------------------------------------------------------------------
extern "C" void kernel_launch(void* const* d_in, const int* in_sizes, int n_in,
                              void* d_out, int out_size)
{
    const float* dns    = (const float*)d_in[0];
    const float* img    = (const float*)d_in[1];
    const float* W_i1   = (const float*)d_in[4];
    const float* w_att1 = (const float*)d_in[5];
    const float* W_d2   = (const float*)d_in[7];
    const float* w_att2 = (const float*)d_in[10];
    float* out = (float*)d_out;

    float *part1, *part2, *vp, *up;
    cudaGetSymbolAddress((void**)&part1, g_part1);
    cudaGetSymbolAddress((void**)&part2, g_part2);
    cudaGetSymbolAddress((void**)&vp, g_vp);
    cudaGetSymbolAddress((void**)&up, g_up);

    __half *dns_h, *img_h, *wi_h, *wd_h;
    cudaGetSymbolAddress((void**)&dns_h, g_dns_h);
    cudaGetSymbolAddress((void**)&img_h, g_img_h);
    cudaGetSymbolAddress((void**)&wi_h, g_wi_h);
    cudaGetSymbolAddress((void**)&wd_h, g_wd_h);

    cudaFuncSetAttribute(gemm_h2, cudaFuncAttributeMaxDynamicSharedMemorySize, SMEM_DYN);

    tohalf4<<<NB_DNS + NB_IMG + 2 * NB_W, 256>>>(dns, dns_h, img, img_h,
                                                 W_i1, wi_h, W_d2, wd_h);

    gemm_h2<<<dim3(NCT, DNS_MT + IMG_MT), 256, SMEM_DYN>>>(
        dns_h, wd_h, w_att2 + HID, part2,
        img_h, wi_h, w_att1 + HID, part1);

    wsum_sm<<<dim3(BATCH, VSPLIT + USPLIT), 256>>>(part1, img_h, part2, dns_h, vp, up);

    finalize<<<dim3(BATCH, NSC), 256>>>(vp, up, (float4*)out);
}

// round 16
// speedup vs baseline: 1.1871x; 1.0018x over previous
#include <cuda_runtime.h>
#include <cuda_fp16.h>
#include <math.h>
#include <stdint.h>

#define HID   1024
#define SEQ   512
#define RIMG  196
#define BATCH 32
#define NCT   8
#define MT    128
#define NT    128
#define KC    64
#define NCHUNK (HID / KC)
#define ROWB  144
#define VERB  (128 * ROWB)
#define STAGEB (2 * VERB)
#define WV_OFF  (2 * STAGEB)
#define RED_OFF (WV_OFF + 512)
#define SMEM_DYN (RED_OFF + 1024 + 256)

#define IMG_MT (BATCH * RIMG / MT)    // 49
#define DNS_MT (BATCH * SEQ / MT)     // 128

#define VSPLIT 7
#define USPLIT 16

// ---------------- scratch ----------------
__device__ float g_part1[NCT * BATCH * RIMG];
__device__ float g_part2[NCT * BATCH * SEQ];
__device__ float g_vp[VSPLIT * BATCH * HID];
__device__ float g_up[USPLIT * BATCH * HID];

__device__ __half g_dns_h[BATCH * SEQ * HID];
__device__ __half g_img_h[BATCH * RIMG * HID];
__device__ __half g_wi_h[HID * HID];
__device__ __half g_wd_h[HID * HID];

// ---------------- streams/events (created pre-checkpoint, pre-capture) ------
struct StreamPack {
    cudaStream_t s1;
    cudaEvent_t e0, ew, e2;
    StreamPack() {
        cudaStreamCreateWithFlags(&s1, cudaStreamNonBlocking);
        cudaEventCreateWithFlags(&e0, cudaEventDisableTiming);
        cudaEventCreateWithFlags(&ew, cudaEventDisableTiming);
        cudaEventCreateWithFlags(&e2, cudaEventDisableTiming);
    }
};
static StreamPack g_sp;

// ---------------- helpers ----------------
__device__ __forceinline__ uint32_t smem_u32(const void* p) {
    uint32_t a;
    asm("{ .reg .u64 t; cvta.to.shared.u64 t, %1; cvt.u32.u64 %0, t; }" : "=r"(a) : "l"(p));
    return a;
}
__device__ __forceinline__ void ldsm4(uint32_t* r, uint32_t addr) {
    asm volatile("ldmatrix.sync.aligned.m8n8.x4.shared.b16 {%0,%1,%2,%3}, [%4];"
                 : "=r"(r[0]), "=r"(r[1]), "=r"(r[2]), "=r"(r[3]) : "r"(addr));
}
__device__ __forceinline__ void mma16816(float* c, const uint32_t* a,
                                         uint32_t b0, uint32_t b1) {
    asm volatile(
        "mma.sync.aligned.m16n8k16.row.col.f32.f16.f16.f32 "
        "{%0,%1,%2,%3}, {%4,%5,%6,%7}, {%8,%9}, {%0,%1,%2,%3};"
        : "+f"(c[0]), "+f"(c[1]), "+f"(c[2]), "+f"(c[3])
        : "r"(a[0]), "r"(a[1]), "r"(a[2]), "r"(a[3]), "r"(b0), "r"(b1));
}
#define CP16(s, g) \
    asm volatile("cp.async.cg.shared.global [%0], [%1], 16;" :: "r"(s), "l"(g) : "memory")
#define CP_COMMIT() asm volatile("cp.async.commit_group;" ::: "memory")

__device__ __forceinline__ float fast_tanh(float x) {
    return 1.f - 2.f / (__expf(2.f * x) + 1.f);
}
__device__ __forceinline__ float warpRedMax(float v) {
#pragma unroll
    for (int o = 16; o > 0; o >>= 1) v = fmaxf(v, __shfl_xor_sync(0xffffffffu, v, o));
    return v;
}
__device__ __forceinline__ float warpRedSum(float v) {
#pragma unroll
    for (int o = 16; o > 0; o >>= 1) v += __shfl_xor_sync(0xffffffffu, v, o);
    return v;
}

__device__ __forceinline__ void cvt16(const float4* p, uint4* o) {
    float4 f[4];
#pragma unroll
    for (int j = 0; j < 4; j++) f[j] = __ldg(p + j);
#pragma unroll
    for (int g = 0; g < 2; g++) {
        float4 a = f[g * 2], c = f[g * 2 + 1];
        __half2 h0 = __floats2half2_rn(a.x, a.y);
        __half2 h1 = __floats2half2_rn(a.z, a.w);
        __half2 h2 = __floats2half2_rn(c.x, c.y);
        __half2 h3 = __floats2half2_rn(c.z, c.w);
        uint4 w;
        w.x = *reinterpret_cast<uint32_t*>(&h0);
        w.y = *reinterpret_cast<uint32_t*>(&h1);
        w.z = *reinterpret_cast<uint32_t*>(&h2);
        w.w = *reinterpret_cast<uint32_t*>(&h3);
        o[g] = w;
    }
}

// ---------------------------------------------------------------------------
#define NB_DNS (BATCH * SEQ * HID / 4096)    // 4096
#define NB_IMG (BATCH * RIMG * HID / 4096)   // 1568
#define NB_W   (HID * HID / 4096)            // 256

// convert dns only (runs on side stream)
__global__ __launch_bounds__(256)
void tohalf_dns(const float* __restrict__ in, __half* __restrict__ out)
{
    const int i = blockIdx.x * 256 + threadIdx.x;
    cvt16((const float4*)in + (size_t)i * 4, (uint4*)out + (size_t)i * 2);
}

// convert img + both weight matrices (runs on default stream)
__global__ __launch_bounds__(256)
void tohalf_small(const float* __restrict__ i0, __half* __restrict__ o0,
                  const float* __restrict__ i1, __half* __restrict__ o1,
                  const float* __restrict__ i2, __half* __restrict__ o2)
{
    const int b = blockIdx.x;
    const float* in; __half* out; int base;
    if (b < NB_IMG)             { in = i0; out = o0; base = b; }
    else if (b < NB_IMG + NB_W) { in = i1; out = o1; base = b - NB_IMG; }
    else                        { in = i2; out = o2; base = b - NB_IMG - NB_W; }
    const int i = base * 256 + threadIdx.x;
    cvt16((const float4*)in + (size_t)i * 4, (uint4*)out + (size_t)i * 2);
}

// ---------------------------------------------------------------------------
// single-path fp16 GEMM (proven R8/R12 core). grid (NCT, mtiles).
// ---------------------------------------------------------------------------
__global__ __launch_bounds__(256, 2)
void gemm_h1(const __half* __restrict__ X, const __half* __restrict__ W,
             const float* __restrict__ wvec, float* __restrict__ part, int Ntot)
{
    extern __shared__ char smem[];
    const uint32_t sb = smem_u32(smem);
    const int tid = threadIdx.x, lane = tid & 31, wid = tid >> 5;
    const int ntile = blockIdx.x, mtile = blockIdx.y;

    float* wvsh = (float*)(smem + WV_OFF);
    float* red  = (float*)(smem + RED_OFF);
    if (tid < 128) wvsh[tid] = wvec[ntile * NT + tid];

    const int row  = tid >> 1;
    const int half = tid & 1;
    const char* pA = (const char*)(X + (size_t)(mtile * MT + row) * HID) + half * 64;
    const char* pB = (const char*)(W + (size_t)(ntile * NT + row) * HID) + half * 64;
    const uint32_t st = (uint32_t)(row * ROWB + half * 64);

    const int m_off = (wid & 3) * 32;
    const int n_off = (wid >> 2) * 64;
    const int lm_row  = lane & 15;
    const int lm_colb = (lane & 16) ? 16 : 0;

    float acc[2][8][4];
#pragma unroll
    for (int t = 0; t < 2; t++)
#pragma unroll
        for (int n = 0; n < 8; n++)
#pragma unroll
            for (int j = 0; j < 4; j++) acc[t][n][j] = 0.f;

#define ISSUE(ci)                                                  \
    do {                                                           \
        const uint32_t s0 = sb + ((ci) & 1) * STAGEB + st;         \
        const char* gA = pA + (size_t)(ci) * 128;                  \
        const char* gB = pB + (size_t)(ci) * 128;                  \
        CP16(s0,      gA);                                         \
        CP16(s0 + 16, gA + 16);                                    \
        CP16(s0 + 32, gA + 32);                                    \
        CP16(s0 + 48, gA + 48);                                    \
        CP16(s0 + VERB,      gB);                                  \
        CP16(s0 + VERB + 16, gB + 16);                             \
        CP16(s0 + VERB + 32, gB + 32);                             \
        CP16(s0 + VERB + 48, gB + 48);                             \
        CP_COMMIT();                                               \
    } while (0)

    ISSUE(0);

    for (int i = 0; i < NCHUNK; ++i) {
        asm volatile("cp.async.wait_group 0;" ::: "memory");
        __syncthreads();
        if (i + 1 < NCHUNK) ISSUE(i + 1);

        const uint32_t SA = sb + (i & 1) * STAGEB;
        const uint32_t SB = SA + VERB;
#pragma unroll
        for (int ks = 0; ks < 4; ks++) {
            const uint32_t aoff = (uint32_t)(ks * 32 + lm_colb);
            uint32_t af[2][4], bf[4][4];
#pragma unroll
            for (int t = 0; t < 2; t++)
                ldsm4(af[t], SA + (uint32_t)((m_off + t * 16 + lm_row) * ROWB) + aoff);
#pragma unroll
            for (int q = 0; q < 4; q++)
                ldsm4(bf[q], SB + (uint32_t)((n_off + q * 16 + lm_row) * ROWB) + aoff);
#pragma unroll
            for (int t = 0; t < 2; t++)
#pragma unroll
                for (int n8 = 0; n8 < 8; n8++) {
                    const int q = n8 >> 1, u = n8 & 1;
                    mma16816(acc[t][n8], af[t], bf[q][u], bf[q][u + 2]);
                }
        }
    }

    float s0[2] = {0.f, 0.f}, s1[2] = {0.f, 0.f};
#pragma unroll
    for (int t = 0; t < 2; t++)
#pragma unroll
        for (int n8 = 0; n8 < 8; n8++) {
            const float w0 = wvsh[n_off + n8 * 8 + (lane & 3) * 2];
            const float w1 = wvsh[n_off + n8 * 8 + (lane & 3) * 2 + 1];
            s0[t] = fmaf(fast_tanh(acc[t][n8][0]), w0, s0[t]);
            s0[t] = fmaf(fast_tanh(acc[t][n8][1]), w1, s0[t]);
            s1[t] = fmaf(fast_tanh(acc[t][n8][2]), w0, s1[t]);
            s1[t] = fmaf(fast_tanh(acc[t][n8][3]), w1, s1[t]);
        }
#pragma unroll
    for (int o = 1; o <= 2; o <<= 1) {
#pragma unroll
        for (int t = 0; t < 2; t++) {
            s0[t] += __shfl_xor_sync(0xffffffffu, s0[t], o);
            s1[t] += __shfl_xor_sync(0xffffffffu, s1[t], o);
        }
    }
    __syncthreads();
    if ((lane & 3) == 0) {
        const int r = lane >> 2;
        float* rw = red + (wid >> 2) * 128;
        rw[m_off + r]          = s0[0];
        rw[m_off + r + 8]      = s1[0];
        rw[m_off + 16 + r]     = s0[1];
        rw[m_off + 16 + r + 8] = s1[1];
    }
    __syncthreads();
    if (tid < 128)
        part[ntile * Ntot + mtile * MT + tid] = red[tid] + red[128 + tid];
}

// ---------------------------------------------------------------------------
// fused softmax + split-r weighted sum, reading the fp16 copies (R15).
// ---------------------------------------------------------------------------
__global__ __launch_bounds__(256)
void wsum_sm(const float* __restrict__ part1, const __half* __restrict__ imgh,
             const float* __restrict__ part2, const __half* __restrict__ dnsh,
             float* __restrict__ vp, float* __restrict__ up)
{
    __shared__ float ws[SEQ];
    __shared__ float sh[8];
    const int b = blockIdx.x, y = blockIdx.y, t = threadIdx.x;

    const float* part; const __half* X; float* outp;
    int r0, rn, n, N;
    if (y < VSPLIT) {
        part = part1; X = imgh; outp = vp + (size_t)y * BATCH * HID;
        r0 = y * (RIMG / VSPLIT); rn = RIMG / VSPLIT; n = RIMG; N = BATCH * RIMG;
    } else {
        const int s = y - VSPLIT;
        part = part2; X = dnsh; outp = up + (size_t)s * BATCH * HID;
        r0 = s * (SEQ / USPLIT); rn = SEQ / USPLIT; n = SEQ; N = BATCH * SEQ;
    }
    const int base = b * n;

    float m = -1e30f;
    for (int i = t; i < n; i += 256) {
        float x = 0.f;
#pragma unroll
        for (int c = 0; c < NCT; c++) x += part[c * N + base + i];
        ws[i] = x;
        m = fmaxf(m, x);
    }
    m = warpRedMax(m);
    if ((t & 31) == 0) sh[t >> 5] = m;
    __syncthreads();
    float M = sh[0];
#pragma unroll
    for (int q = 1; q < 8; q++) M = fmaxf(M, sh[q]);

    float sum = 0.f;
    for (int i = t; i < n; i += 256) {
        float e = expf(ws[i] - M);
        ws[i] = e;
        sum += e;
    }
    sum = warpRedSum(sum);
    __syncthreads();
    if ((t & 31) == 0) sh[t >> 5] = sum;
    __syncthreads();
    float S = 0.f;
#pragma unroll
    for (int q = 0; q < 8; q++) S += sh[q];
    const float inv = 1.f / S;
    __syncthreads();

    const uint2* xb = (const uint2*)(X + (size_t)b * n * HID) + (size_t)r0 * 256 + t;
    float4 acc = make_float4(0.f, 0.f, 0.f, 0.f);
#pragma unroll 4
    for (int r = 0; r < rn; r++) {
        const float wr = ws[r0 + r];
        const uint2 h4 = __ldg(&xb[(size_t)r * 256]);
        const __half2 hA = *reinterpret_cast<const __half2*>(&h4.x);
        const __half2 hB = *reinterpret_cast<const __half2*>(&h4.y);
        const float2 fA = __half22float2(hA);
        const float2 fB = __half22float2(hB);
        acc.x = fmaf(wr, fA.x, acc.x);
        acc.y = fmaf(wr, fA.y, acc.y);
        acc.z = fmaf(wr, fB.x, acc.z);
        acc.w = fmaf(wr, fB.y, acc.w);
    }
    acc.x *= inv; acc.y *= inv; acc.z *= inv; acc.w *= inv;
    ((float4*)(outp + b * HID))[t] = acc;
}

// ---------------------------------------------------------------------------
// finalize: reduce partials -> u,v in regs, broadcast over s-range.
// ---------------------------------------------------------------------------
#define NSC 8
#define SCHUNK (SEQ / NSC)    // 64
__global__ __launch_bounds__(256)
void finalize(const float* __restrict__ vp, const float* __restrict__ up,
              float4* __restrict__ out)
{
    const int b = blockIdx.x, sc = blockIdx.y, t = threadIdx.x;

    float4 sv = make_float4(0.f, 0.f, 0.f, 0.f);
#pragma unroll
    for (int s = 0; s < VSPLIT; s++) {
        float4 x = __ldg(((const float4*)(vp + (size_t)s * BATCH * HID + b * HID)) + t);
        sv.x += x.x; sv.y += x.y; sv.z += x.z; sv.w += x.w;
    }
    float4 su = make_float4(0.f, 0.f, 0.f, 0.f);
#pragma unroll
    for (int s = 0; s < USPLIT; s++) {
        float4 x = __ldg(((const float4*)(up + (size_t)s * BATCH * HID + b * HID)) + t);
        su.x += x.x; su.y += x.y; su.z += x.z; su.w += x.w;
    }

    float4* ou = out + ((size_t)b * SEQ + sc * SCHUNK) * 256 + t;
    float4* ov = ou + (size_t)BATCH * SEQ * 256;
#pragma unroll 4
    for (int s = 0; s < SCHUNK; s++) {
        ou[(size_t)s * 256] = su;
        ov[(size_t)s * 256] = sv;
    }
}

// ---------------------------------------------------------------------------
extern "C" void kernel_launch(void* const* d_in, const int* in_sizes, int n_in,
                              void* d_out, int out_size)
{
    const float* dns    = (const float*)d_in[0];
    const float* img    = (const float*)d_in[1];
    const float* W_i1   = (const float*)d_in[4];
    const float* w_att1 = (const float*)d_in[5];
    const float* W_d2   = (const float*)d_in[7];
    const float* w_att2 = (const float*)d_in[10];
    float* out = (float*)d_out;

    float *part1, *part2, *vp, *up;
    cudaGetSymbolAddress((void**)&part1, g_part1);
    cudaGetSymbolAddress((void**)&part2, g_part2);
    cudaGetSymbolAddress((void**)&vp, g_vp);
    cudaGetSymbolAddress((void**)&up, g_up);

    __half *dns_h, *img_h, *wi_h, *wd_h;
    cudaGetSymbolAddress((void**)&dns_h, g_dns_h);
    cudaGetSymbolAddress((void**)&img_h, g_img_h);
    cudaGetSymbolAddress((void**)&wi_h, g_wi_h);
    cudaGetSymbolAddress((void**)&wd_h, g_wd_h);

    cudaFuncSetAttribute(gemm_h1, cudaFuncAttributeMaxDynamicSharedMemorySize, SMEM_DYN);

    // fork side stream off the (possibly capturing) default stream
    cudaEventRecord(g_sp.e0, 0);
    cudaStreamWaitEvent(g_sp.s1, g_sp.e0, 0);

    // s1: convert dns (big, memory-bound)
    tohalf_dns<<<NB_DNS, 256, 0, g_sp.s1>>>(dns, dns_h);

    // default: convert img + weights, then img GEMM (compute, overlaps dns cvt)
    tohalf_small<<<NB_IMG + 2 * NB_W, 256>>>(img, img_h, W_i1, wi_h, W_d2, wd_h);
    cudaEventRecord(g_sp.ew, 0);
    gemm_h1<<<dim3(NCT, IMG_MT), 256, SMEM_DYN>>>(img_h, wi_h, w_att1 + HID,
                                                  part1, BATCH * RIMG);

    // s1: dns GEMM once dns_h + weights ready (concurrent with img GEMM tail)
    cudaStreamWaitEvent(g_sp.s1, g_sp.ew, 0);
    gemm_h1<<<dim3(NCT, DNS_MT), 256, SMEM_DYN, g_sp.s1>>>(dns_h, wd_h, w_att2 + HID,
                                                           part2, BATCH * SEQ);
    cudaEventRecord(g_sp.e2, g_sp.s1);

    // join and finish on default stream
    cudaStreamWaitEvent(0, g_sp.e2, 0);
    wsum_sm<<<dim3(BATCH, VSPLIT + USPLIT), 256>>>(part1, img_h, part2, dns_h, vp, up);
    finalize<<<dim3(BATCH, NSC), 256>>>(vp, up, (float4*)out);
}

// round 17
// speedup vs baseline: 1.2163x; 1.0246x over previous
#include <cuda_runtime.h>
#include <cuda_fp16.h>
#include <math.h>
#include <stdint.h>

#define HID   1024
#define SEQ   512
#define RIMG  196
#define BATCH 32
#define NCT   8
#define MT    64
#define NT    128
#define KC    64
#define NCHUNK (HID / KC)
#define ROWB  144
#define A_VERB (64 * ROWB)            // 9216
#define B_VERB (128 * ROWB)           // 18432
#define STAGEB (A_VERB + B_VERB)      // 27648
#define WV_OFF  (2 * STAGEB)          // 55296
#define RED_OFF (WV_OFF + 512)
#define SMEM_DYN (RED_OFF + 1024 + 128)   // ~57 KB -> 3 CTAs/SM

#define IMG_MT (BATCH * RIMG / MT)    // 98
#define DNS_MT (BATCH * SEQ / MT)     // 256

#define VSPLIT 7
#define USPLIT 16

// ---------------- scratch ----------------
__device__ float g_part1[NCT * BATCH * RIMG];
__device__ float g_part2[NCT * BATCH * SEQ];
__device__ float g_vp[VSPLIT * BATCH * HID];
__device__ float g_up[USPLIT * BATCH * HID];

__device__ __half g_dns_h[BATCH * SEQ * HID];
__device__ __half g_img_h[BATCH * RIMG * HID];
__device__ __half g_wi_h[HID * HID];
__device__ __half g_wd_h[HID * HID];

// ---------------- streams/events ----------------
struct StreamPack {
    cudaStream_t s1;
    cudaEvent_t e0, ew, e2;
    StreamPack() {
        cudaStreamCreateWithFlags(&s1, cudaStreamNonBlocking);
        cudaEventCreateWithFlags(&e0, cudaEventDisableTiming);
        cudaEventCreateWithFlags(&ew, cudaEventDisableTiming);
        cudaEventCreateWithFlags(&e2, cudaEventDisableTiming);
    }
};
static StreamPack g_sp;

// ---------------- helpers ----------------
__device__ __forceinline__ uint32_t smem_u32(const void* p) {
    uint32_t a;
    asm("{ .reg .u64 t; cvta.to.shared.u64 t, %1; cvt.u32.u64 %0, t; }" : "=r"(a) : "l"(p));
    return a;
}
__device__ __forceinline__ void ldsm4(uint32_t* r, uint32_t addr) {
    asm volatile("ldmatrix.sync.aligned.m8n8.x4.shared.b16 {%0,%1,%2,%3}, [%4];"
                 : "=r"(r[0]), "=r"(r[1]), "=r"(r[2]), "=r"(r[3]) : "r"(addr));
}
__device__ __forceinline__ void mma16816(float* c, const uint32_t* a,
                                         uint32_t b0, uint32_t b1) {
    asm volatile(
        "mma.sync.aligned.m16n8k16.row.col.f32.f16.f16.f32 "
        "{%0,%1,%2,%3}, {%4,%5,%6,%7}, {%8,%9}, {%0,%1,%2,%3};"
        : "+f"(c[0]), "+f"(c[1]), "+f"(c[2]), "+f"(c[3])
        : "r"(a[0]), "r"(a[1]), "r"(a[2]), "r"(a[3]), "r"(b0), "r"(b1));
}
#define CP16(s, g) \
    asm volatile("cp.async.cg.shared.global [%0], [%1], 16;" :: "r"(s), "l"(g) : "memory")
#define CP_COMMIT() asm volatile("cp.async.commit_group;" ::: "memory")

__device__ __forceinline__ float fast_tanh(float x) {
    return 1.f - 2.f / (__expf(2.f * x) + 1.f);
}
__device__ __forceinline__ float warpRedMax(float v) {
#pragma unroll
    for (int o = 16; o > 0; o >>= 1) v = fmaxf(v, __shfl_xor_sync(0xffffffffu, v, o));
    return v;
}
__device__ __forceinline__ float warpRedSum(float v) {
#pragma unroll
    for (int o = 16; o > 0; o >>= 1) v += __shfl_xor_sync(0xffffffffu, v, o);
    return v;
}

__device__ __forceinline__ void cvt16(const float4* p, uint4* o) {
    float4 f[4];
#pragma unroll
    for (int j = 0; j < 4; j++) f[j] = __ldg(p + j);
#pragma unroll
    for (int g = 0; g < 2; g++) {
        float4 a = f[g * 2], c = f[g * 2 + 1];
        __half2 h0 = __floats2half2_rn(a.x, a.y);
        __half2 h1 = __floats2half2_rn(a.z, a.w);
        __half2 h2 = __floats2half2_rn(c.x, c.y);
        __half2 h3 = __floats2half2_rn(c.z, c.w);
        uint4 w;
        w.x = *reinterpret_cast<uint32_t*>(&h0);
        w.y = *reinterpret_cast<uint32_t*>(&h1);
        w.z = *reinterpret_cast<uint32_t*>(&h2);
        w.w = *reinterpret_cast<uint32_t*>(&h3);
        o[g] = w;
    }
}

// ---------------------------------------------------------------------------
#define NB_DNS (BATCH * SEQ * HID / 4096)    // 4096
#define NB_IMG (BATCH * RIMG * HID / 4096)   // 1568
#define NB_W   (HID * HID / 4096)            // 256

__global__ __launch_bounds__(256)
void tohalf_dns(const float* __restrict__ in, __half* __restrict__ out)
{
    const int i = blockIdx.x * 256 + threadIdx.x;
    cvt16((const float4*)in + (size_t)i * 4, (uint4*)out + (size_t)i * 2);
}

__global__ __launch_bounds__(256)
void tohalf_small(const float* __restrict__ i0, __half* __restrict__ o0,
                  const float* __restrict__ i1, __half* __restrict__ o1,
                  const float* __restrict__ i2, __half* __restrict__ o2)
{
    const int b = blockIdx.x;
    const float* in; __half* out; int base;
    if (b < NB_IMG)             { in = i0; out = o0; base = b; }
    else if (b < NB_IMG + NB_W) { in = i1; out = o1; base = b - NB_IMG; }
    else                        { in = i2; out = o2; base = b - NB_IMG - NB_W; }
    const int i = base * 256 + threadIdx.x;
    cvt16((const float4*)in + (size_t)i * 4, (uint4*)out + (size_t)i * 2);
}

// ---------------------------------------------------------------------------
// fp16 GEMM, CTA tile 64x128, warp tile 32x32 (2m x 4n warps), occ 3.
// ---------------------------------------------------------------------------
__global__ __launch_bounds__(256, 3)
void gemm_h1(const __half* __restrict__ X, const __half* __restrict__ W,
             const float* __restrict__ wvec, float* __restrict__ part, int Ntot)
{
    extern __shared__ char smem[];
    const uint32_t sb = smem_u32(smem);
    const int tid = threadIdx.x, lane = tid & 31, wid = tid >> 5;
    const int ntile = blockIdx.x, mtile = blockIdx.y;

    float* wvsh = (float*)(smem + WV_OFF);
    float* red  = (float*)(smem + RED_OFF);
    if (tid < 128) wvsh[tid] = wvec[ntile * NT + tid];

    // cp.async mapping:
    //  A: row = tid>>2 (0..63),  seg = (tid&3)*32  (2x CP16)
    //  B: row = tid>>1 (0..127), seg = (tid&1)*64  (4x CP16)
    const int arow = tid >> 2, aseg = (tid & 3) * 32;
    const int brow = tid >> 1, bseg = (tid & 1) * 64;
    const char* pA = (const char*)(X + (size_t)(mtile * MT + arow) * HID) + aseg;
    const char* pB = (const char*)(W + (size_t)(ntile * NT + brow) * HID) + bseg;
    const uint32_t stA = (uint32_t)(arow * ROWB + aseg);
    const uint32_t stB = (uint32_t)(A_VERB + brow * ROWB + bseg);

    const int m_off = (wid & 1) * 32;
    const int n_off = (wid >> 1) * 32;
    const int lm_row  = lane & 15;
    const int lm_colb = (lane & 16) ? 16 : 0;

    float acc[2][4][4];
#pragma unroll
    for (int t = 0; t < 2; t++)
#pragma unroll
        for (int n = 0; n < 4; n++)
#pragma unroll
            for (int j = 0; j < 4; j++) acc[t][n][j] = 0.f;

#define ISSUE(ci)                                                  \
    do {                                                           \
        const uint32_t s0 = sb + ((ci) & 1) * STAGEB;              \
        const char* gA = pA + (size_t)(ci) * 128;                  \
        const char* gB = pB + (size_t)(ci) * 128;                  \
        CP16(s0 + stA,      gA);                                   \
        CP16(s0 + stA + 16, gA + 16);                              \
        CP16(s0 + stB,      gB);                                   \
        CP16(s0 + stB + 16, gB + 16);                              \
        CP16(s0 + stB + 32, gB + 32);                              \
        CP16(s0 + stB + 48, gB + 48);                              \
        CP_COMMIT();                                               \
    } while (0)

    ISSUE(0);

    for (int i = 0; i < NCHUNK; ++i) {
        asm volatile("cp.async.wait_group 0;" ::: "memory");
        __syncthreads();
        if (i + 1 < NCHUNK) ISSUE(i + 1);

        const uint32_t SA = sb + (i & 1) * STAGEB;
        const uint32_t SB = SA + A_VERB;
#pragma unroll
        for (int ks = 0; ks < 4; ks++) {
            const uint32_t aoff = (uint32_t)(ks * 32 + lm_colb);
            uint32_t af[2][4], bf[2][4];
#pragma unroll
            for (int t = 0; t < 2; t++)
                ldsm4(af[t], SA + (uint32_t)((m_off + t * 16 + lm_row) * ROWB) + aoff);
#pragma unroll
            for (int q = 0; q < 2; q++)
                ldsm4(bf[q], SB + (uint32_t)((n_off + q * 16 + lm_row) * ROWB) + aoff);
#pragma unroll
            for (int t = 0; t < 2; t++)
#pragma unroll
                for (int n8 = 0; n8 < 4; n8++) {
                    const int q = n8 >> 1, u = n8 & 1;
                    mma16816(acc[t][n8], af[t], bf[q][u], bf[q][u + 2]);
                }
        }
    }

    // epilogue: tanh + dot(wv) -> per-row partials
    float s0[2] = {0.f, 0.f}, s1[2] = {0.f, 0.f};
#pragma unroll
    for (int t = 0; t < 2; t++)
#pragma unroll
        for (int n8 = 0; n8 < 4; n8++) {
            const float w0 = wvsh[n_off + n8 * 8 + (lane & 3) * 2];
            const float w1 = wvsh[n_off + n8 * 8 + (lane & 3) * 2 + 1];
            s0[t] = fmaf(fast_tanh(acc[t][n8][0]), w0, s0[t]);
            s0[t] = fmaf(fast_tanh(acc[t][n8][1]), w1, s0[t]);
            s1[t] = fmaf(fast_tanh(acc[t][n8][2]), w0, s1[t]);
            s1[t] = fmaf(fast_tanh(acc[t][n8][3]), w1, s1[t]);
        }
#pragma unroll
    for (int o = 1; o <= 2; o <<= 1) {
#pragma unroll
        for (int t = 0; t < 2; t++) {
            s0[t] += __shfl_xor_sync(0xffffffffu, s0[t], o);
            s1[t] += __shfl_xor_sync(0xffffffffu, s1[t], o);
        }
    }
    __syncthreads();
    if ((lane & 3) == 0) {
        const int r = lane >> 2;
        float* rw = red + (wid >> 1) * 64;     // n-group row block
        rw[m_off + r]          = s0[0];
        rw[m_off + r + 8]      = s1[0];
        rw[m_off + 16 + r]     = s0[1];
        rw[m_off + 16 + r + 8] = s1[1];
    }
    __syncthreads();
    if (tid < 64)
        part[ntile * Ntot + mtile * MT + tid] =
            red[tid] + red[64 + tid] + red[128 + tid] + red[192 + tid];
}

// ---------------------------------------------------------------------------
// fused softmax + split-r weighted sum, reading the fp16 copies (R15).
// ---------------------------------------------------------------------------
__global__ __launch_bounds__(256)
void wsum_sm(const float* __restrict__ part1, const __half* __restrict__ imgh,
             const float* __restrict__ part2, const __half* __restrict__ dnsh,
             float* __restrict__ vp, float* __restrict__ up)
{
    __shared__ float ws[SEQ];
    __shared__ float sh[8];
    const int b = blockIdx.x, y = blockIdx.y, t = threadIdx.x;

    const float* part; const __half* X; float* outp;
    int r0, rn, n, N;
    if (y < VSPLIT) {
        part = part1; X = imgh; outp = vp + (size_t)y * BATCH * HID;
        r0 = y * (RIMG / VSPLIT); rn = RIMG / VSPLIT; n = RIMG; N = BATCH * RIMG;
    } else {
        const int s = y - VSPLIT;
        part = part2; X = dnsh; outp = up + (size_t)s * BATCH * HID;
        r0 = s * (SEQ / USPLIT); rn = SEQ / USPLIT; n = SEQ; N = BATCH * SEQ;
    }
    const int base = b * n;

    float m = -1e30f;
    for (int i = t; i < n; i += 256) {
        float x = 0.f;
#pragma unroll
        for (int c = 0; c < NCT; c++) x += part[c * N + base + i];
        ws[i] = x;
        m = fmaxf(m, x);
    }
    m = warpRedMax(m);
    if ((t & 31) == 0) sh[t >> 5] = m;
    __syncthreads();
    float M = sh[0];
#pragma unroll
    for (int q = 1; q < 8; q++) M = fmaxf(M, sh[q]);

    float sum = 0.f;
    for (int i = t; i < n; i += 256) {
        float e = expf(ws[i] - M);
        ws[i] = e;
        sum += e;
    }
    sum = warpRedSum(sum);
    __syncthreads();
    if ((t & 31) == 0) sh[t >> 5] = sum;
    __syncthreads();
    float S = 0.f;
#pragma unroll
    for (int q = 0; q < 8; q++) S += sh[q];
    const float inv = 1.f / S;
    __syncthreads();

    const uint2* xb = (const uint2*)(X + (size_t)b * n * HID) + (size_t)r0 * 256 + t;
    float4 acc = make_float4(0.f, 0.f, 0.f, 0.f);
#pragma unroll 4
    for (int r = 0; r < rn; r++) {
        const float wr = ws[r0 + r];
        const uint2 h4 = __ldg(&xb[(size_t)r * 256]);
        const __half2 hA = *reinterpret_cast<const __half2*>(&h4.x);
        const __half2 hB = *reinterpret_cast<const __half2*>(&h4.y);
        const float2 fA = __half22float2(hA);
        const float2 fB = __half22float2(hB);
        acc.x = fmaf(wr, fA.x, acc.x);
        acc.y = fmaf(wr, fA.y, acc.y);
        acc.z = fmaf(wr, fB.x, acc.z);
        acc.w = fmaf(wr, fB.y, acc.w);
    }
    acc.x *= inv; acc.y *= inv; acc.z *= inv; acc.w *= inv;
    ((float4*)(outp + b * HID))[t] = acc;
}

// ---------------------------------------------------------------------------
#define NSC 8
#define SCHUNK (SEQ / NSC)    // 64
__global__ __launch_bounds__(256)
void finalize(const float* __restrict__ vp, const float* __restrict__ up,
              float4* __restrict__ out)
{
    const int b = blockIdx.x, sc = blockIdx.y, t = threadIdx.x;

    float4 sv = make_float4(0.f, 0.f, 0.f, 0.f);
#pragma unroll
    for (int s = 0; s < VSPLIT; s++) {
        float4 x = __ldg(((const float4*)(vp + (size_t)s * BATCH * HID + b * HID)) + t);
        sv.x += x.x; sv.y += x.y; sv.z += x.z; sv.w += x.w;
    }
    float4 su = make_float4(0.f, 0.f, 0.f, 0.f);
#pragma unroll
    for (int s = 0; s < USPLIT; s++) {
        float4 x = __ldg(((const float4*)(up + (size_t)s * BATCH * HID + b * HID)) + t);
        su.x += x.x; su.y += x.y; su.z += x.z; su.w += x.w;
    }

    float4* ou = out + ((size_t)b * SEQ + sc * SCHUNK) * 256 + t;
    float4* ov = ou + (size_t)BATCH * SEQ * 256;
#pragma unroll 4
    for (int s = 0; s < SCHUNK; s++) {
        ou[(size_t)s * 256] = su;
        ov[(size_t)s * 256] = sv;
    }
}

// ---------------------------------------------------------------------------
extern "C" void kernel_launch(void* const* d_in, const int* in_sizes, int n_in,
                              void* d_out, int out_size)
{
    const float* dns    = (const float*)d_in[0];
    const float* img    = (const float*)d_in[1];
    const float* W_i1   = (const float*)d_in[4];
    const float* w_att1 = (const float*)d_in[5];
    const float* W_d2   = (const float*)d_in[7];
    const float* w_att2 = (const float*)d_in[10];
    float* out = (float*)d_out;

    float *part1, *part2, *vp, *up;
    cudaGetSymbolAddress((void**)&part1, g_part1);
    cudaGetSymbolAddress((void**)&part2, g_part2);
    cudaGetSymbolAddress((void**)&vp, g_vp);
    cudaGetSymbolAddress((void**)&up, g_up);

    __half *dns_h, *img_h, *wi_h, *wd_h;
    cudaGetSymbolAddress((void**)&dns_h, g_dns_h);
    cudaGetSymbolAddress((void**)&img_h, g_img_h);
    cudaGetSymbolAddress((void**)&wi_h, g_wi_h);
    cudaGetSymbolAddress((void**)&wd_h, g_wd_h);

    cudaFuncSetAttribute(gemm_h1, cudaFuncAttributeMaxDynamicSharedMemorySize, SMEM_DYN);

    // fork side stream off the default stream
    cudaEventRecord(g_sp.e0, 0);
    cudaStreamWaitEvent(g_sp.s1, g_sp.e0, 0);

    // s1: convert dns (big, memory-bound)
    tohalf_dns<<<NB_DNS, 256, 0, g_sp.s1>>>(dns, dns_h);

    // default: convert img + weights, then img GEMM
    tohalf_small<<<NB_IMG + 2 * NB_W, 256>>>(img, img_h, W_i1, wi_h, W_d2, wd_h);
    cudaEventRecord(g_sp.ew, 0);
    gemm_h1<<<dim3(NCT, IMG_MT), 256, SMEM_DYN>>>(img_h, wi_h, w_att1 + HID,
                                                  part1, BATCH * RIMG);

    // s1: dns GEMM once dns_h + weights ready
    cudaStreamWaitEvent(g_sp.s1, g_sp.ew, 0);
    gemm_h1<<<dim3(NCT, DNS_MT), 256, SMEM_DYN, g_sp.s1>>>(dns_h, wd_h, w_att2 + HID,
                                                           part2, BATCH * SEQ);
    cudaEventRecord(g_sp.e2, g_sp.s1);

    // join and finish on default stream
    cudaStreamWaitEvent(0, g_sp.e2, 0);
    wsum_sm<<<dim3(BATCH, VSPLIT + USPLIT), 256>>>(part1, img_h, part2, dns_h, vp, up);
    finalize<<<dim3(BATCH, NSC), 256>>>(vp, up, (float4*)out);
}